// round 15
// baseline (speedup 1.0000x reference)
#include <cuda_runtime.h>
#include <cuda_bf16.h>

#define BB 4
#define SS 512
#define EE 512
#define UU 256

// ---------------- scratch (__device__ globals) ----------------
__device__ float g_K[BB * SS * UU];            // key_pre + b1
__device__ float g_Q[BB * SS * UU];            // qry_pre
__device__ float g_S[BB * SS * SS];            // raw scores (fp32)
__device__ float g_part[4 * 2048 * 512];       // 16MB split-K partials

// bf16 hi/lo planes, u32 = (bf16 x_{2k+1} << 16) | bf16 x_{2k}
__device__ unsigned g_AH[2 * 2048 * 256];      // h1,h2 row-major
__device__ unsigned g_AL[2 * 2048 * 256];
__device__ unsigned g_WH[2 * 256 * 256];       // w transposed
__device__ unsigned g_WL[2 * 256 * 256];
__device__ unsigned g_TH[4 * 512 * 256];       // h1 transposed
__device__ unsigned g_TL[4 * 512 * 256];
__device__ unsigned g_SH[2048 * 256];          // softmax probs
__device__ unsigned g_SL[2048 * 256];

// ---------------- helpers ----------------
__device__ __forceinline__ float tanh_ap(float x) {
    float y; asm("tanh.approx.f32 %0,%1;" : "=f"(y) : "f"(x)); return y;
}
__device__ __forceinline__ float ex2_ap(float x) {
    float y; asm("ex2.approx.f32 %0,%1;" : "=f"(y) : "f"(x)); return y;
}
__device__ __forceinline__ void cp16(void* dst, const void* src) {
    unsigned d = (unsigned)__cvta_generic_to_shared(dst);
    asm volatile("cp.async.ca.shared.global [%0],[%1],16;" :: "r"(d), "l"(src) : "memory");
}
__device__ __forceinline__ void bsplit2(float x0, float x1, unsigned& hi, unsigned& lo) {
    asm("cvt.rn.bf16x2.f32 %0, %1, %2;" : "=r"(hi) : "f"(x1), "f"(x0));
    float b0 = __uint_as_float(hi << 16);
    float b1 = __uint_as_float(hi & 0xffff0000u);
    float l0 = x0 - b0;
    float l1 = x1 - b1;
    asm("cvt.rn.bf16x2.f32 %0, %1, %2;" : "=r"(lo) : "f"(l1), "f"(l0));
}
__device__ __forceinline__ void mma16816(float* c, const unsigned* a,
                                         unsigned b0, unsigned b1) {
    asm volatile(
        "mma.sync.aligned.m16n8k16.row.col.f32.bf16.bf16.f32 "
        "{%0,%1,%2,%3}, {%4,%5,%6,%7}, {%8,%9}, {%0,%1,%2,%3};"
        : "+f"(c[0]), "+f"(c[1]), "+f"(c[2]), "+f"(c[3])
        : "r"(a[0]), "r"(a[1]), "r"(a[2]), "r"(a[3]), "r"(b0), "r"(b1));
}
__device__ __forceinline__ void ldm_x4(unsigned* r, const unsigned* smem_ptr) {
    unsigned a = (unsigned)__cvta_generic_to_shared(smem_ptr);
    asm volatile("ldmatrix.sync.aligned.m8n8.x4.shared.b16 {%0,%1,%2,%3}, [%4];"
                 : "=r"(r[0]), "=r"(r[1]), "=r"(r[2]), "=r"(r[3]) : "r"(a));
}

// ---------------- shared-memory role structs ----------------
struct MmaSmem {                 // 40960 B
    unsigned sA[2][2][64][20];
    unsigned sB[2][2][64][20];
};
struct ScoresSmem {              // 33792 B
    float4 q4[32][32];
    float4 k4[32][33];
    float4 v4s[32];
};

// ---------------------------------------------------------------------------
// mma tile body (R14 k32 version, smem passed in)
// ---------------------------------------------------------------------------
__device__ __forceinline__ void mma_tile(
    const unsigned* __restrict__ AH, const unsigned* __restrict__ AL,
    const unsigned* __restrict__ BH, const unsigned* __restrict__ BL,
    float* __restrict__ P, int ldp, int row0, int col0, int ku0,
    MmaSmem* sm)
{
    const int tid = threadIdx.x;
    const int w = tid >> 5, lane = tid & 31;
    const int wm = w >> 1, wn = w & 1;
    const int g = lane >> 2, t = lane & 3;
    const int fr = tid >> 2;
    const int fc = (tid & 3) << 2;

    const int a_row = 32 * wm + (lane & 15);
    const int a_colb = (lane & 16) ? 4 : 0;
    const int b_row = 32 * wn + ((lane & 16) ? 8 : 0) + (lane & 7);
    const int b_colb = (lane & 8) ? 4 : 0;

    const unsigned* arH = AH + (size_t)(row0 + fr) * 256 + ku0 + fc;
    const unsigned* arL = AL + (size_t)(row0 + fr) * 256 + ku0 + fc;
    const unsigned* brH = BH + (size_t)(col0 + fr) * 256 + ku0 + fc;
    const unsigned* brL = BL + (size_t)(col0 + fr) * 256 + ku0 + fc;

    float acc[2][4][4];
#pragma unroll
    for (int mi = 0; mi < 2; mi++)
#pragma unroll
        for (int nt = 0; nt < 4; nt++)
#pragma unroll
            for (int j = 0; j < 4; j++) acc[mi][nt][j] = 0.f;

#pragma unroll
    for (int rh = 0; rh < 2; rh++) {
        const int off = rh * 32 * 256;
        cp16(&sm->sA[0][0][fr + 32 * rh][fc], arH + off);
        cp16(&sm->sA[0][1][fr + 32 * rh][fc], arL + off);
        cp16(&sm->sB[0][0][fr + 32 * rh][fc], brH + off);
        cp16(&sm->sB[0][1][fr + 32 * rh][fc], brL + off);
    }
    asm volatile("cp.async.commit_group;");

#pragma unroll 1
    for (int c = 0; c < 4; c++) {
        const int buf = c & 1;
        asm volatile("cp.async.wait_group 0;");
        __syncthreads();
        if (c < 3) {
            const int nb = buf ^ 1;
            const int koff = (c + 1) * 16;
#pragma unroll
            for (int rh = 0; rh < 2; rh++) {
                const int off = rh * 32 * 256 + koff;
                cp16(&sm->sA[nb][0][fr + 32 * rh][fc], arH + off);
                cp16(&sm->sA[nb][1][fr + 32 * rh][fc], arL + off);
                cp16(&sm->sB[nb][0][fr + 32 * rh][fc], brH + off);
                cp16(&sm->sB[nb][1][fr + 32 * rh][fc], brL + off);
            }
            asm volatile("cp.async.commit_group;");
        }

#pragma unroll
        for (int h = 0; h < 2; h++) {
            const int a_col = 8 * h + a_colb;
            const int b_col = 8 * h + b_colb;
            unsigned aH[2][4], aL[2][4], bH[2][4], bL[2][4];
            ldm_x4(aH[0], &sm->sA[buf][0][a_row][a_col]);
            ldm_x4(aH[1], &sm->sA[buf][0][16 + a_row][a_col]);
            ldm_x4(aL[0], &sm->sA[buf][1][a_row][a_col]);
            ldm_x4(aL[1], &sm->sA[buf][1][16 + a_row][a_col]);
            ldm_x4(bH[0], &sm->sB[buf][0][b_row][b_col]);
            ldm_x4(bH[1], &sm->sB[buf][0][16 + b_row][b_col]);
            ldm_x4(bL[0], &sm->sB[buf][1][b_row][b_col]);
            ldm_x4(bL[1], &sm->sB[buf][1][16 + b_row][b_col]);

#pragma unroll
            for (int mi = 0; mi < 2; mi++)
#pragma unroll
                for (int hh = 0; hh < 2; hh++)
#pragma unroll
                    for (int s = 0; s < 2; s++) {
                        const int nt = 2 * hh + s;
                        mma16816(acc[mi][nt], aH[mi], bH[hh][2 * s], bH[hh][2 * s + 1]);
                        mma16816(acc[mi][nt], aH[mi], bL[hh][2 * s], bL[hh][2 * s + 1]);
                        mma16816(acc[mi][nt], aL[mi], bH[hh][2 * s], bH[hh][2 * s + 1]);
                    }
        }
    }

#pragma unroll
    for (int mi = 0; mi < 2; mi++) {
        const int orow = row0 + 32 * wm + 16 * mi + g;
#pragma unroll
        for (int nt = 0; nt < 4; nt++) {
            const int ocol = col0 + 32 * wn + 8 * nt + 2 * t;
            *(float2*)&P[(size_t)orow * ldp + ocol] =
                make_float2(acc[mi][nt][0], acc[mi][nt][1]);
            *(float2*)&P[(size_t)(orow + 8) * ldp + ocol] =
                make_float2(acc[mi][nt][2], acc[mi][nt][3]);
        }
    }
}

__device__ __forceinline__ void pv_body(int b, int bx, int by, int ks, MmaSmem* sm)
{
    float* P = g_part + (size_t)ks * 2048 * 512 + (size_t)b * 512 * 512;
    mma_tile(g_SH + (size_t)b * 131072, g_SL + (size_t)b * 131072,
             g_TH + (size_t)b * 131072, g_TL + (size_t)b * 131072,
             P, 512, by * 64, bx * 64, ks * 64, sm);
}

// ---------------------------------------------------------------------------
// scores body (R14, per batch; b2 dropped)
// ---------------------------------------------------------------------------
__device__ __forceinline__ void scores_body(const float* __restrict__ v,
                                            int b, int jt, int it, ScoresSmem* s)
{
    const int tid = threadIdx.x;
    const int jl = tid & 31;
    const int ib = tid >> 5;

    const float* Qb = g_Q + ((size_t)(b * SS + it * 32)) * UU;
    const float* Kb = g_K + ((size_t)(b * SS + jt * 32)) * UU;

    float acc[4] = {0.f, 0.f, 0.f, 0.f};

    for (int uc = 0; uc < 2; uc++) {
        const int base = uc * 32;
        for (int tix = tid; tix < 32 * 32; tix += 256) {
            const int r = tix >> 5, c = tix & 31;
            s->q4[r][c] = ((const float4*)(Qb + (size_t)r * UU))[base + c];
            s->k4[r][c] = ((const float4*)(Kb + (size_t)r * UU))[base + c];
        }
        if (tid < 32) s->v4s[tid] = ((const float4*)v)[base + tid];
        __syncthreads();

#pragma unroll 4
        for (int c = 0; c < 32; c++) {
            const float4 kv = s->k4[jl][c];
            const float4 vv = s->v4s[c];
#pragma unroll
            for (int r = 0; r < 4; r++) {
                const float4 qv = s->q4[ib + 8 * r][c];
                acc[r] += vv.x * tanh_ap(qv.x + kv.x);
                acc[r] += vv.y * tanh_ap(qv.y + kv.y);
                acc[r] += vv.z * tanh_ap(qv.z + kv.z);
                acc[r] += vv.w * tanh_ap(qv.w + kv.w);
            }
        }
        __syncthreads();
    }

#pragma unroll
    for (int r = 0; r < 4; r++) {
        const int i = it * 32 + ib + 8 * r;
        g_S[((size_t)(b * SS + i)) * SS + jt * 32 + jl] = acc[r];
    }
}

// h1 [b][j][e] -> transposed bf16 planes (one 32x32 tile per idx)
__device__ __forceinline__ void h1t_body(const float* __restrict__ h1,
                                         int idx, char* buf)
{
    float (*tsm)[33] = (float(*)[33])buf;
    const int tx = threadIdx.x & 31, ty = threadIdx.x >> 5;
    const int r0 = (idx & 15) * 32;           // j
    const int c0 = ((idx >> 4) & 15) * 32;    // e
    const int b  = idx >> 8;
    const float* src = h1 + (size_t)b * SS * EE;
#pragma unroll
    for (int j = 0; j < 4; j++)
        tsm[ty + 8 * j][tx] = src[(size_t)(r0 + ty + 8 * j) * EE + c0 + tx];
    __syncthreads();
    const int oc = threadIdx.x >> 3;
    const int p  = threadIdx.x & 7;
    unsigned* oH = g_TH + (size_t)b * 131072;
    unsigned* oL = g_TL + (size_t)b * 131072;
    const size_t base = (size_t)(c0 + oc) * 256 + (r0 >> 1);
    unsigned h0, l0, h1u, l1u;
    bsplit2(tsm[2 * p][oc],      tsm[2 * p + 1][oc],  h0, l0);
    bsplit2(tsm[2 * p + 16][oc], tsm[2 * p + 17][oc], h1u, l1u);
    oH[base + p] = h0;      oL[base + p] = l0;
    oH[base + p + 8] = h1u; oL[base + p + 8] = l1u;
}

// softmax body for one row (emits bf16 hi/lo planes)
__device__ __forceinline__ void softmax_body(int row)
{
    __shared__ float sm8[8];
    __shared__ float ssum[8];
    const float* s = g_S + (size_t)row * SS;
    const int tid = threadIdx.x;

    const float2 vv = ((const float2*)s)[tid];
    float m = fmaxf(vv.x, vv.y);
#pragma unroll
    for (int o = 16; o > 0; o >>= 1) m = fmaxf(m, __shfl_xor_sync(0xffffffffu, m, o));
    if ((tid & 31) == 0) sm8[tid >> 5] = m;
    __syncthreads();
    float bm = sm8[0];
#pragma unroll
    for (int i = 1; i < 8; i++) bm = fmaxf(bm, sm8[i]);

    const float L2E = 1.4426950408889634f;
    float e0 = ex2_ap((vv.x - bm) * L2E);
    float e1 = ex2_ap((vv.y - bm) * L2E);
    float su = e0 + e1;
#pragma unroll
    for (int o = 16; o > 0; o >>= 1) su += __shfl_xor_sync(0xffffffffu, su, o);
    if ((tid & 31) == 0) ssum[tid >> 5] = su;
    __syncthreads();
    float bs = 0.f;
#pragma unroll
    for (int i = 0; i < 8; i++) bs += ssum[i];

    const float inv = 1.0f / bs;
    unsigned h, l;
    bsplit2(e0 * inv, e1 * inv, h, l);
    g_SH[(size_t)row * 256 + tid] = h;
    g_SL[(size_t)row * 256 + tid] = l;
}

// pv split-K reduce for one float4 slot
__device__ __forceinline__ void pvred_body(float* __restrict__ out, int i4)
{
    const float4* p = (const float4*)g_part + i4;
    float4 s0 = p[0];
    float4 s1 = p[262144];
    float4 s2 = p[524288];
    float4 s3 = p[786432];
    ((float4*)out)[i4] = make_float4((s0.x + s1.x) + (s2.x + s3.x),
                                     (s0.y + s1.y) + (s2.y + s3.y),
                                     (s0.z + s1.z) + (s2.z + s3.z),
                                     (s0.w + s1.w) + (s2.w + s3.w));
}

// ---------------------------------------------------------------------------
// Kernel 1: conversions needed by qk (rows + wT). grid 2304.
// ---------------------------------------------------------------------------
__global__ void __launch_bounds__(256)
conv_main(const float* __restrict__ h1, const float* __restrict__ h2,
          const float* __restrict__ w)
{
    __shared__ float tsm[32][33];
    const int bid = blockIdx.x;

    if (bid < 2048) {
        const int i = bid * 256 + threadIdx.x;
        float4 v = (i < 262144) ? ((const float4*)h1)[i]
                                : ((const float4*)h2)[i - 262144];
        unsigned h0, l0, h1u, l1u;
        bsplit2(v.x, v.y, h0, l0);
        bsplit2(v.z, v.w, h1u, l1u);
        ((uint2*)g_AH)[i] = make_uint2(h0, h1u);
        ((uint2*)g_AL)[i] = make_uint2(l0, l1u);
        return;
    }

    const int idx = bid - 2048;
    const int tx = threadIdx.x & 31, ty = threadIdx.x >> 5;
    const int c0 = (idx & 7) * 32;        // u
    const int r0 = (idx >> 3) * 32;       // e' in [0,1024)
#pragma unroll
    for (int j = 0; j < 4; j++)
        tsm[ty + 8 * j][tx] = w[(size_t)(r0 + ty + 8 * j) * UU + c0 + tx];
    __syncthreads();
    const int oc = threadIdx.x >> 3;
    const int p  = threadIdx.x & 7;
    const int which = r0 >> 9;
    const int rl = r0 & 511;
    unsigned* oH = g_WH + which * 65536;
    unsigned* oL = g_WL + which * 65536;
    const size_t base = (size_t)(c0 + oc) * 256 + (rl >> 1);
    unsigned h0, l0, h1u, l1u;
    bsplit2(tsm[2 * p][oc],      tsm[2 * p + 1][oc],  h0, l0);
    bsplit2(tsm[2 * p + 16][oc], tsm[2 * p + 17][oc], h1u, l1u);
    oH[base + p] = h0;      oL[base + p] = l0;
    oH[base + p + 8] = h1u; oL[base + p + 8] = l1u;
}

// Kernel 2: qk split-K mma. grid (4, 32, 8), 128 thr.
__global__ void __launch_bounds__(128)
qk_mma_split()
{
    __shared__ MmaSmem sm;
    const int which = blockIdx.z >> 2;
    const int ks    = blockIdx.z & 3;
    float* P = g_part + (size_t)(ks * 2 + which) * 2048 * 256;
    mma_tile(g_AH + (size_t)which * 524288, g_AL + (size_t)which * 524288,
             g_WH + which * 65536, g_WL + which * 65536,
             P, 256, blockIdx.y * 64, blockIdx.x * 64, ks * 64, &sm);
}

// Kernel 3: qk reduce -> g_K (+b1), g_Q. grid 1024.
__global__ void __launch_bounds__(256)
qk_reduce(const float* __restrict__ b1)
{
    const int tt = blockIdx.x * 256 + threadIdx.x;
    const int which = tt >> 17;
    const int i4 = tt & 131071;
    const float4* p = (const float4*)g_part + (size_t)which * 131072 + i4;
    float4 s0 = p[0];
    float4 s1 = p[262144];
    float4 s2 = p[524288];
    float4 s3 = p[786432];
    float4 o = make_float4((s0.x + s1.x) + (s2.x + s3.x),
                           (s0.y + s1.y) + (s2.y + s3.y),
                           (s0.z + s1.z) + (s2.z + s3.z),
                           (s0.w + s1.w) + (s2.w + s3.w));
    if (which == 0) {
        const float4 bv = ((const float4*)b1)[i4 & 63];
        o.x += bv.x; o.y += bv.y; o.z += bv.z; o.w += bv.w;
        ((float4*)g_K)[i4] = o;
    } else {
        ((float4*)g_Q)[i4] = o;
    }
}

// Kernel 4: h1T conversion (short, first) + scores(b=0). grid 1280, 256 thr.
__global__ void __launch_bounds__(256)
scores0_h1t(const float* __restrict__ v, const float* __restrict__ h1)
{
    __shared__ __align__(16) char buf[sizeof(ScoresSmem)];
    if (blockIdx.x < 1024) {
        h1t_body(h1, blockIdx.x, buf);
    } else {
        const int idx = blockIdx.x - 1024;
        scores_body(v, 0, idx & 15, idx >> 4, (ScoresSmem*)buf);
    }
}

// Kernel 5 (x3): pv(pb) (short, first) + scores(sb). grid 512, 256 thr.
__global__ void __launch_bounds__(256)
scores_pv(const float* __restrict__ v, int sb, int pb)
{
    __shared__ __align__(16) char buf[sizeof(MmaSmem)];
    if (blockIdx.x < 256) {
        if (threadIdx.x >= 128) return;
        const int idx = blockIdx.x;
        pv_body(pb, idx & 7, (idx >> 3) & 7, idx >> 6, (MmaSmem*)buf);
    } else {
        const int idx = blockIdx.x - 256;
        scores_body(v, sb, idx & 15, idx >> 4, (ScoresSmem*)buf);
    }
}

// Kernel 6 (x4): softmax(sb) + optional pv_reduce(rb). grid 512 or 768.
__global__ void __launch_bounds__(256)
softmax_red(float* __restrict__ out, int sb, int rb)
{
    if (blockIdx.x < 512) {
        softmax_body(sb * SS + blockIdx.x);
    } else {
        pvred_body(out, rb * 65536 + (blockIdx.x - 512) * 256 + threadIdx.x);
    }
}

// Kernel 7: final pv(b=3). grid 256, 128 thr.
__global__ void __launch_bounds__(128)
pv_only(int b)
{
    __shared__ MmaSmem sm;
    const int idx = blockIdx.x;
    pv_body(b, idx & 7, (idx >> 3) & 7, idx >> 6, &sm);
}

// Kernel 8: final pv_reduce(b=3). grid 256.
__global__ void __launch_bounds__(256)
pv_red_last(float* __restrict__ out)
{
    pvred_body(out, 3 * 65536 + blockIdx.x * 256 + threadIdx.x);
}

extern "C" void kernel_launch(void* const* d_in, const int* in_sizes, int n_in,
                              void* d_out, int out_size)
{
    const float* h1 = (const float*)d_in[0];
    const float* h2 = (const float*)d_in[1];
    const float* w  = (const float*)d_in[2];
    const float* b1 = (const float*)d_in[3];
    const float* v  = (const float*)d_in[4];
    // b2 (d_in[5]) unused: softmax is shift-invariant.
    float* out = (float*)d_out;

    conv_main<<<2304, 256>>>(h1, h2, w);
    qk_mma_split<<<dim3(4, 32, 8), 128>>>();
    qk_reduce<<<1024, 256>>>(b1);

    scores0_h1t<<<1280, 256>>>(v, h1);        // h1T + scores(0)
    softmax_red<<<512, 256>>>(out, 0, 0);     // softmax(0) only

    scores_pv<<<512, 256>>>(v, 1, 0);         // scores(1) || pv(0)
    softmax_red<<<768, 256>>>(out, 1, 0);     // softmax(1) + pv_reduce(0)

    scores_pv<<<512, 256>>>(v, 2, 1);         // scores(2) || pv(1)
    softmax_red<<<768, 256>>>(out, 2, 1);     // softmax(2) + pv_reduce(1)

    scores_pv<<<512, 256>>>(v, 3, 2);         // scores(3) || pv(2)
    softmax_red<<<768, 256>>>(out, 3, 2);     // softmax(3) + pv_reduce(2)

    pv_only<<<256, 128>>>(3);
    pv_red_last<<<256, 256>>>(out);
}

// round 16
// speedup vs baseline: 1.5001x; 1.5001x over previous
#include <cuda_runtime.h>
#include <cuda_bf16.h>

#define BB 4
#define SS 512
#define EE 512
#define UU 256

// ---------------- scratch (__device__ globals) ----------------
__device__ float g_S[BB * SS * SS];            // raw scores (fp32)
__device__ float g_part[4 * 2048 * 512];       // 16MB split-K partials

// Q,K as packed f16x2 pairs [row][u-pair] (1MB each)
__device__ unsigned g_QH[2048 * 128];
__device__ unsigned g_KH[2048 * 128];

// bf16 hi/lo planes, u32 = (bf16 x_{2k+1} << 16) | bf16 x_{2k}
__device__ unsigned g_AH[2 * 2048 * 256];      // h1,h2 row-major
__device__ unsigned g_AL[2 * 2048 * 256];
__device__ unsigned g_WH[2 * 256 * 256];       // w transposed
__device__ unsigned g_WL[2 * 256 * 256];
__device__ unsigned g_TH[4 * 512 * 256];       // h1 transposed
__device__ unsigned g_TL[4 * 512 * 256];
__device__ unsigned g_SH[2048 * 256];          // softmax probs
__device__ unsigned g_SL[2048 * 256];

// ---------------- helpers ----------------
__device__ __forceinline__ float ex2_ap(float x) {
    float y; asm("ex2.approx.f32 %0,%1;" : "=f"(y) : "f"(x)); return y;
}
__device__ __forceinline__ void cp16(void* dst, const void* src) {
    unsigned d = (unsigned)__cvta_generic_to_shared(dst);
    asm volatile("cp.async.ca.shared.global [%0],[%1],16;" :: "r"(d), "l"(src) : "memory");
}
__device__ __forceinline__ void bsplit2(float x0, float x1, unsigned& hi, unsigned& lo) {
    asm("cvt.rn.bf16x2.f32 %0, %1, %2;" : "=r"(hi) : "f"(x1), "f"(x0));
    float b0 = __uint_as_float(hi << 16);
    float b1 = __uint_as_float(hi & 0xffff0000u);
    float l0 = x0 - b0;
    float l1 = x1 - b1;
    asm("cvt.rn.bf16x2.f32 %0, %1, %2;" : "=r"(lo) : "f"(l1), "f"(l0));
}
__device__ __forceinline__ void mma16816(float* c, const unsigned* a,
                                         unsigned b0, unsigned b1) {
    asm volatile(
        "mma.sync.aligned.m16n8k16.row.col.f32.bf16.bf16.f32 "
        "{%0,%1,%2,%3}, {%4,%5,%6,%7}, {%8,%9}, {%0,%1,%2,%3};"
        : "+f"(c[0]), "+f"(c[1]), "+f"(c[2]), "+f"(c[3])
        : "r"(a[0]), "r"(a[1]), "r"(a[2]), "r"(a[3]), "r"(b0), "r"(b1));
}
__device__ __forceinline__ void ldm_x4(unsigned* r, const unsigned* smem_ptr) {
    unsigned a = (unsigned)__cvta_generic_to_shared(smem_ptr);
    asm volatile("ldmatrix.sync.aligned.m8n8.x4.shared.b16 {%0,%1,%2,%3}, [%4];"
                 : "=r"(r[0]), "=r"(r[1]), "=r"(r[2]), "=r"(r[3]) : "r"(a));
}
// f16x2 tanh term: acc += v0*tanh(q+k).lo + v1*tanh(q+k).hi  (fp32 accumulate)
__device__ __forceinline__ void pair_acc(float& a, unsigned qv, unsigned kv,
                                         float v0, float v1) {
    unsigned x, t;
    asm("add.rn.f16x2 %0,%1,%2;" : "=r"(x) : "r"(qv), "r"(kv));
    asm("tanh.approx.f16x2 %0,%1;" : "=r"(t) : "r"(x));
    float f0, f1;
    asm("{\n\t.reg .b16 lo,hi;\n\tmov.b32 {lo,hi}, %2;\n\t"
        "cvt.f32.f16 %0, lo;\n\tcvt.f32.f16 %1, hi;\n\t}"
        : "=f"(f0), "=f"(f1) : "r"(t));
    a = fmaf(v0, f0, a);
    a = fmaf(v1, f1, a);
}

// ---------------------------------------------------------------------------
// Merged conversion kernel (R14, unchanged): grid 3328 CTAs x 256 threads.
// ---------------------------------------------------------------------------
__global__ void __launch_bounds__(256)
conv_all(const float* __restrict__ h1, const float* __restrict__ h2,
         const float* __restrict__ w)
{
    __shared__ float tsm[32][33];
    const int bid = blockIdx.x;

    if (bid < 2048) {
        const int i = bid * 256 + threadIdx.x;
        float4 v = (i < 262144) ? ((const float4*)h1)[i]
                                : ((const float4*)h2)[i - 262144];
        unsigned h0, l0, h1u, l1u;
        bsplit2(v.x, v.y, h0, l0);
        bsplit2(v.z, v.w, h1u, l1u);
        ((uint2*)g_AH)[i] = make_uint2(h0, h1u);
        ((uint2*)g_AL)[i] = make_uint2(l0, l1u);
        return;
    }

    const int tx = threadIdx.x & 31, ty = threadIdx.x >> 5;
    const int oc = threadIdx.x >> 3;
    const int p  = threadIdx.x & 7;

    if (bid < 2304) {
        const int idx = bid - 2048;
        const int c0 = (idx & 7) * 32;
        const int r0 = (idx >> 3) * 32;
#pragma unroll
        for (int j = 0; j < 4; j++)
            tsm[ty + 8 * j][tx] = w[(size_t)(r0 + ty + 8 * j) * UU + c0 + tx];
        __syncthreads();
        const int which = r0 >> 9;
        const int rl = r0 & 511;
        unsigned* oH = g_WH + which * 65536;
        unsigned* oL = g_WL + which * 65536;
        const size_t base = (size_t)(c0 + oc) * 256 + (rl >> 1);
        unsigned h0, l0, h1u, l1u;
        bsplit2(tsm[2 * p][oc],      tsm[2 * p + 1][oc],  h0, l0);
        bsplit2(tsm[2 * p + 16][oc], tsm[2 * p + 17][oc], h1u, l1u);
        oH[base + p] = h0;      oL[base + p] = l0;
        oH[base + p + 8] = h1u; oL[base + p + 8] = l1u;
        return;
    }

    {
        const int idx = bid - 2304;
        const int r0 = (idx & 15) * 32;
        const int c0 = ((idx >> 4) & 15) * 32;
        const int b  = idx >> 8;
        const float* src = h1 + (size_t)b * SS * EE;
#pragma unroll
        for (int j = 0; j < 4; j++)
            tsm[ty + 8 * j][tx] = src[(size_t)(r0 + ty + 8 * j) * EE + c0 + tx];
        __syncthreads();
        unsigned* oH = g_TH + (size_t)b * 131072;
        unsigned* oL = g_TL + (size_t)b * 131072;
        const size_t base = (size_t)(c0 + oc) * 256 + (r0 >> 1);
        unsigned h0, l0, h1u, l1u;
        bsplit2(tsm[2 * p][oc],      tsm[2 * p + 1][oc],  h0, l0);
        bsplit2(tsm[2 * p + 16][oc], tsm[2 * p + 17][oc], h1u, l1u);
        oH[base + p] = h0;      oL[base + p] = l0;
        oH[base + p + 8] = h1u; oL[base + p + 8] = l1u;
    }
}

// ---------------------------------------------------------------------------
// mma tile (R14 k32 version, unchanged — measured best).
// ---------------------------------------------------------------------------
__device__ __forceinline__ void mma_tile(
    const unsigned* __restrict__ AH, const unsigned* __restrict__ AL,
    const unsigned* __restrict__ BH, const unsigned* __restrict__ BL,
    float* __restrict__ P, int ldp, int row0, int col0, int ku0)
{
    __shared__ unsigned sA[2][2][64][20];
    __shared__ unsigned sB[2][2][64][20];

    const int tid = threadIdx.x;
    const int w = tid >> 5, lane = tid & 31;
    const int wm = w >> 1, wn = w & 1;
    const int g = lane >> 2, t = lane & 3;
    const int fr = tid >> 2;
    const int fc = (tid & 3) << 2;

    const int a_row = 32 * wm + (lane & 15);
    const int a_colb = (lane & 16) ? 4 : 0;
    const int b_row = 32 * wn + ((lane & 16) ? 8 : 0) + (lane & 7);
    const int b_colb = (lane & 8) ? 4 : 0;

    const unsigned* arH = AH + (size_t)(row0 + fr) * 256 + ku0 + fc;
    const unsigned* arL = AL + (size_t)(row0 + fr) * 256 + ku0 + fc;
    const unsigned* brH = BH + (size_t)(col0 + fr) * 256 + ku0 + fc;
    const unsigned* brL = BL + (size_t)(col0 + fr) * 256 + ku0 + fc;

    float acc[2][4][4];
#pragma unroll
    for (int mi = 0; mi < 2; mi++)
#pragma unroll
        for (int nt = 0; nt < 4; nt++)
#pragma unroll
            for (int j = 0; j < 4; j++) acc[mi][nt][j] = 0.f;

#pragma unroll
    for (int rh = 0; rh < 2; rh++) {
        const int off = rh * 32 * 256;
        cp16(&sA[0][0][fr + 32 * rh][fc], arH + off);
        cp16(&sA[0][1][fr + 32 * rh][fc], arL + off);
        cp16(&sB[0][0][fr + 32 * rh][fc], brH + off);
        cp16(&sB[0][1][fr + 32 * rh][fc], brL + off);
    }
    asm volatile("cp.async.commit_group;");

#pragma unroll 1
    for (int c = 0; c < 4; c++) {
        const int buf = c & 1;
        asm volatile("cp.async.wait_group 0;");
        __syncthreads();
        if (c < 3) {
            const int nb = buf ^ 1;
            const int koff = (c + 1) * 16;
#pragma unroll
            for (int rh = 0; rh < 2; rh++) {
                const int off = rh * 32 * 256 + koff;
                cp16(&sA[nb][0][fr + 32 * rh][fc], arH + off);
                cp16(&sA[nb][1][fr + 32 * rh][fc], arL + off);
                cp16(&sB[nb][0][fr + 32 * rh][fc], brH + off);
                cp16(&sB[nb][1][fr + 32 * rh][fc], brL + off);
            }
            asm volatile("cp.async.commit_group;");
        }

#pragma unroll
        for (int h = 0; h < 2; h++) {
            const int a_col = 8 * h + a_colb;
            const int b_col = 8 * h + b_colb;
            unsigned aH[2][4], aL[2][4], bH[2][4], bL[2][4];
            ldm_x4(aH[0], &sA[buf][0][a_row][a_col]);
            ldm_x4(aH[1], &sA[buf][0][16 + a_row][a_col]);
            ldm_x4(aL[0], &sA[buf][1][a_row][a_col]);
            ldm_x4(aL[1], &sA[buf][1][16 + a_row][a_col]);
            ldm_x4(bH[0], &sB[buf][0][b_row][b_col]);
            ldm_x4(bH[1], &sB[buf][0][16 + b_row][b_col]);
            ldm_x4(bL[0], &sB[buf][1][b_row][b_col]);
            ldm_x4(bL[1], &sB[buf][1][16 + b_row][b_col]);

#pragma unroll
            for (int mi = 0; mi < 2; mi++)
#pragma unroll
                for (int hh = 0; hh < 2; hh++)
#pragma unroll
                    for (int s = 0; s < 2; s++) {
                        const int nt = 2 * hh + s;
                        mma16816(acc[mi][nt], aH[mi], bH[hh][2 * s], bH[hh][2 * s + 1]);
                        mma16816(acc[mi][nt], aH[mi], bL[hh][2 * s], bL[hh][2 * s + 1]);
                        mma16816(acc[mi][nt], aL[mi], bH[hh][2 * s], bH[hh][2 * s + 1]);
                    }
        }
    }

#pragma unroll
    for (int mi = 0; mi < 2; mi++) {
        const int orow = row0 + 32 * wm + 16 * mi + g;
#pragma unroll
        for (int nt = 0; nt < 4; nt++) {
            const int ocol = col0 + 32 * wn + 8 * nt + 2 * t;
            *(float2*)&P[(size_t)orow * ldp + ocol] =
                make_float2(acc[mi][nt][0], acc[mi][nt][1]);
            *(float2*)&P[(size_t)(orow + 8) * ldp + ocol] =
                make_float2(acc[mi][nt][2], acc[mi][nt][3]);
        }
    }
}

// Stage 1a: qk split-K mma (unchanged).
__global__ void __launch_bounds__(128)
qk_mma_split()
{
    const int which = blockIdx.z >> 2;
    const int ks    = blockIdx.z & 3;
    float* P = g_part + (size_t)(ks * 2 + which) * 2048 * 256;
    mma_tile(g_AH + (size_t)which * 524288, g_AL + (size_t)which * 524288,
             g_WH + which * 65536, g_WL + which * 65536,
             P, 256, blockIdx.y * 64, blockIdx.x * 64, ks * 64);
}

// Stage 1b: reduce partials -> packed f16x2 Q,K (K gets +b1). grid 1024.
__global__ void __launch_bounds__(256)
qk_reduce(const float* __restrict__ b1)
{
    const int tt = blockIdx.x * 256 + threadIdx.x;
    const int which = tt >> 17;
    const int i4 = tt & 131071;
    const float4* p = (const float4*)g_part + (size_t)which * 131072 + i4;
    float4 s0 = p[0];
    float4 s1 = p[262144];
    float4 s2 = p[524288];
    float4 s3 = p[786432];
    float4 o = make_float4((s0.x + s1.x) + (s2.x + s3.x),
                           (s0.y + s1.y) + (s2.y + s3.y),
                           (s0.z + s1.z) + (s2.z + s3.z),
                           (s0.w + s1.w) + (s2.w + s3.w));
    if (which == 0) {
        const float4 bv = ((const float4*)b1)[i4 & 63];
        o.x += bv.x; o.y += bv.y; o.z += bv.z; o.w += bv.w;
    }
    unsigned p0, p1;
    asm("cvt.rn.f16x2.f32 %0, %1, %2;" : "=r"(p0) : "f"(o.y), "f"(o.x));
    asm("cvt.rn.f16x2.f32 %0, %1, %2;" : "=r"(p1) : "f"(o.w), "f"(o.z));
    if (which == 0) ((uint2*)g_KH)[i4] = make_uint2(p0, p1);
    else            ((uint2*)g_QH)[i4] = make_uint2(p0, p1);
}

// Stage 3a: pv split-K mma (unchanged).
__global__ void __launch_bounds__(128)
pv_mma_split()
{
    const int b  = blockIdx.z >> 2;
    const int ks = blockIdx.z & 3;
    float* P = g_part + (size_t)ks * 2048 * 512 + (size_t)b * 512 * 512;
    mma_tile(g_SH + (size_t)b * 131072, g_SL + (size_t)b * 131072,
             g_TH + (size_t)b * 131072, g_TL + (size_t)b * 131072,
             P, 512, blockIdx.y * 64, blockIdx.x * 64, ks * 64);
}

// Stage 3b: reduce partials -> out (unchanged). grid 1024.
__global__ void __launch_bounds__(256)
pv_reduce(float* __restrict__ out)
{
    const int i4 = blockIdx.x * 256 + threadIdx.x;
    const float4* p = (const float4*)g_part + i4;
    float4 s0 = p[0];
    float4 s1 = p[262144];
    float4 s2 = p[524288];
    float4 s3 = p[786432];
    ((float4*)out)[i4] = make_float4((s0.x + s1.x) + (s2.x + s3.x),
                                     (s0.y + s1.y) + (s2.y + s3.y),
                                     (s0.z + s1.z) + (s2.z + s3.z),
                                     (s0.w + s1.w) + (s2.w + s3.w));
}

// ---------------------------------------------------------------------------
// Stage 2a: scores via tanh.approx.f16x2 (2 elems/MUFU op), fp32 accumulate.
// Q,K read as packed f16x2 planes. K tile stored TRANSPOSED in smem so the
// hot k read (k2t[c][jl]) is conflict-free. b2 dropped.
// grid (16 jt, 16 it, 4 b), block 256.
// ---------------------------------------------------------------------------
__global__ void __launch_bounds__(256)
scores_kernel(const float* __restrict__ v)
{
    __shared__ uint4 q2[32][32];    // [i-row][u-quad] (8 u per quad)
    __shared__ uint4 k2t[32][33];   // [u-quad][j-row] transposed, padded
    __shared__ float4 v4s[64];      // v fp32

    const int b  = blockIdx.z;
    const int it = blockIdx.y;
    const int jt = blockIdx.x;
    const int tid = threadIdx.x;
    const int jl = tid & 31;
    const int ib = tid >> 5;

    const uint4* Qb = (const uint4*)g_QH + (size_t)(b * SS + it * 32) * 32;
    const uint4* Kb = (const uint4*)g_KH + (size_t)(b * SS + jt * 32) * 32;

#pragma unroll
    for (int i = 0; i < 4; i++) {
        const int idx = tid + i * 256;
        const int r = idx >> 5, c = idx & 31;
        q2[r][c]  = Qb[(size_t)r * 32 + c];
        k2t[c][r] = Kb[(size_t)r * 32 + c];
    }
    if (tid < 64) v4s[tid] = ((const float4*)v)[tid];
    __syncthreads();

    float acc[4] = {0.f, 0.f, 0.f, 0.f};

#pragma unroll 4
    for (int c = 0; c < 32; c++) {
        const uint4 kw = k2t[c][jl];
        const float4 va = v4s[2 * c];
        const float4 vb = v4s[2 * c + 1];
#pragma unroll
        for (int r = 0; r < 4; r++) {
            const uint4 qw = q2[ib + 8 * r][c];   // warp broadcast
            pair_acc(acc[r], qw.x, kw.x, va.x, va.y);
            pair_acc(acc[r], qw.y, kw.y, va.z, va.w);
            pair_acc(acc[r], qw.z, kw.z, vb.x, vb.y);
            pair_acc(acc[r], qw.w, kw.w, vb.z, vb.w);
        }
    }

#pragma unroll
    for (int r = 0; r < 4; r++) {
        const int i = it * 32 + ib + 8 * r;
        g_S[((size_t)(b * SS + i)) * SS + jt * 32 + jl] = acc[r];
    }
}

// Stage 2b: row softmax -> bf16 hi/lo planes (unchanged). grid 2048.
__global__ void __launch_bounds__(256)
softmax2()
{
    const int row = blockIdx.x;
    const float* s = g_S + (size_t)row * SS;
    const int tid = threadIdx.x;

    const float2 vv = ((const float2*)s)[tid];
    float m = fmaxf(vv.x, vv.y);
#pragma unroll
    for (int o = 16; o > 0; o >>= 1) m = fmaxf(m, __shfl_xor_sync(0xffffffffu, m, o));
    __shared__ float sm[8];
    __shared__ float ssum[8];
    if ((tid & 31) == 0) sm[tid >> 5] = m;
    __syncthreads();
    float bm = sm[0];
#pragma unroll
    for (int i = 1; i < 8; i++) bm = fmaxf(bm, sm[i]);

    const float L2E = 1.4426950408889634f;
    float e0 = ex2_ap((vv.x - bm) * L2E);
    float e1 = ex2_ap((vv.y - bm) * L2E);
    float su = e0 + e1;
#pragma unroll
    for (int o = 16; o > 0; o >>= 1) su += __shfl_xor_sync(0xffffffffu, su, o);
    if ((tid & 31) == 0) ssum[tid >> 5] = su;
    __syncthreads();
    float bs = 0.f;
#pragma unroll
    for (int i = 0; i < 8; i++) bs += ssum[i];

    const float inv = 1.0f / bs;
    unsigned h, l;
    bsplit2(e0 * inv, e1 * inv, h, l);
    g_SH[(size_t)row * 256 + tid] = h;
    g_SL[(size_t)row * 256 + tid] = l;
}

extern "C" void kernel_launch(void* const* d_in, const int* in_sizes, int n_in,
                              void* d_out, int out_size)
{
    const float* h1 = (const float*)d_in[0];
    const float* h2 = (const float*)d_in[1];
    const float* w  = (const float*)d_in[2];
    const float* b1 = (const float*)d_in[3];
    const float* v  = (const float*)d_in[4];
    // b2 (d_in[5]) unused: softmax is shift-invariant.
    float* out = (float*)d_out;

    conv_all<<<3328, 256>>>(h1, h2, w);

    qk_mma_split<<<dim3(4, 32, 8), 128>>>();
    qk_reduce<<<1024, 256>>>(b1);

    scores_kernel<<<dim3(16, 16, 4), 256>>>(v);
    softmax2<<<2048, 256>>>();

    pv_mma_split<<<dim3(8, 8, 16), 128>>>();
    pv_reduce<<<1024, 256>>>(out);
}